// round 13
// baseline (speedup 1.0000x reference)
#include <cuda_runtime.h>
#include <math.h>

// ---------------------------------------------------------------------------
// Aggregator: counting-sort CSR (16B-aligned segments) + MIO-lean reductions.
// Accum reads edge metadata via uniform int4 loads SOFTWARE-PIPELINED one
// iteration ahead (meta latency hidden behind current group's gathers).
// Output (float32): [entity_agg 100000*64 | user_agg 50000*64 | latent_new 8*64]
// ---------------------------------------------------------------------------

#define N_ENT 100000
#define N_USR 50000
#define N_EDG 2000000
#define N_NNZ 2000000
#define SCAN_CHUNK 1024
#define NBLK_E ((N_ENT + SCAN_CHUNK - 1) / SCAN_CHUNK)   // 98
#define NBLK_U ((N_USR + SCAN_CHUNK - 1) / SCAN_CHUNK)   // 49

__device__ int  g_cntE[N_ENT];
__device__ int  g_cntU[N_USR];
__device__ int  g_offE[N_ENT + 1];
__device__ int  g_offU[N_USR + 1];
__device__ int  g_curE[N_ENT];
__device__ int  g_curU[N_USR];
__device__ int  g_bsum[NBLK_E + NBLK_U];
// padded storage: segments padded to 4-int (entity) / 2-int2 (user) alignment
__device__ __align__(16) int  g_skgp[N_EDG + 4 * N_ENT];
__device__ __align__(16) int2 g_sit[N_NNZ + 2 * N_USR];

__device__ float g_latent_lin[8 * 64];
__device__ float g_latent_new[8 * 64];

// smem layout for fused accum kernel (floats)
#define OFF_W1T 0              // 64 * 66 transposed+padded W1
#define OFF_LAT 4224           // 8 * 64
#define OFF_LN  4736           // 8 * 64
#define OFF_SU  5248           // 8 warps * 64
#define OFF_B1  5760           // 64
#define OFF_WUA 5824           // 64
#define OFF_BUA 5888           // 8
#define SMEM_FLOATS 5896

// ---------------------------------------------------------------------------
__global__ void hist_kernel(const int* __restrict__ eidx,
                            const int* __restrict__ irow,
                            int nE, int nnz) {
    int i = blockIdx.x * blockDim.x + threadIdx.x;
    if (i < nE) atomicAdd(&g_cntE[eidx[i]], 1);
    else { int j = i - nE; if (j < nnz) atomicAdd(&g_cntU[irow[j]], 1); }
}

// per-block reduce of ALIGNED counts (entity: pad to 4, user: pad to 2)
__global__ void scan_reduce_kernel(int nEnt, int nUsr) {
    __shared__ int s[256];
    int b = blockIdx.x, t = threadIdx.x;
    const int* src; int base, n, pad;
    if (b < NBLK_E) { src = g_cntE; base = b * SCAN_CHUNK; n = nEnt; pad = 3; }
    else            { src = g_cntU; base = (b - NBLK_E) * SCAN_CHUNK; n = nUsr; pad = 1; }
    int sum = 0;
    for (int i = t; i < SCAN_CHUNK; i += 256) {
        int idx = base + i;
        if (idx < n) sum += (src[idx] + pad) & ~pad;
    }
    s[t] = sum; __syncthreads();
    for (int d = 128; d > 0; d >>= 1) { if (t < d) s[t] += s[t + d]; __syncthreads(); }
    if (t == 0) g_bsum[b] = s[0];
}

// ---------------------------------------------------------------------------
// Warp 0 scans block sums (shfl); all 256 threads then run the latent chain.
__global__ __launch_bounds__(256) void scan_mid_latent_kernel(
        const float* __restrict__ lat,
        const float* __restrict__ wgt,
        const float* __restrict__ W1, const float* __restrict__ b1,
        const float* __restrict__ W2, const float* __restrict__ b2,
        const float* __restrict__ Wwa, const float* __restrict__ bwa,
        float* __restrict__ out_latent,
        int nEnt, int nUsr) {
    __shared__ float A[8][64];
    __shared__ float B[16][64];
    __shared__ float S[8][16];
    __shared__ float D[8][16];
    const unsigned FULL = 0xffffffffu;
    int tid = threadIdx.x;

    if (tid < 32) {
        int lane = tid;
        {
            int v[4]; int tsum = 0;
            #pragma unroll
            for (int k = 0; k < 4; k++) {
                int idx = lane * 4 + k;
                v[k] = (idx < NBLK_E) ? g_bsum[idx] : 0;
                tsum += v[k];
            }
            int sc = tsum;
            #pragma unroll
            for (int off = 1; off < 32; off <<= 1) {
                int o = __shfl_up_sync(FULL, sc, off);
                if (lane >= off) sc += o;
            }
            int run = sc - tsum;
            #pragma unroll
            for (int k = 0; k < 4; k++) {
                int idx = lane * 4 + k;
                if (idx < NBLK_E) g_bsum[idx] = run;
                run += v[k];
            }
            if (lane == 31) g_offE[nEnt] = sc;
        }
        {
            int v[4]; int tsum = 0;
            #pragma unroll
            for (int k = 0; k < 4; k++) {
                int idx = lane * 4 + k;
                v[k] = (idx < NBLK_U) ? g_bsum[NBLK_E + idx] : 0;
                tsum += v[k];
            }
            int sc = tsum;
            #pragma unroll
            for (int off = 1; off < 32; off <<= 1) {
                int o = __shfl_up_sync(FULL, sc, off);
                if (lane >= off) sc += o;
            }
            int run = sc - tsum;
            #pragma unroll
            for (int k = 0; k < 4; k++) {
                int idx = lane * 4 + k;
                if (idx < NBLK_U) g_bsum[NBLK_E + idx] = run;
                run += v[k];
            }
            if (lane == 31) g_offU[nUsr] = sc;
        }
    }

    // ---- latent chain ----
    for (int idx = tid; idx < 8 * 64; idx += 256) {
        int f = idx >> 6, j = idx & 63;
        float s = b2[j];
        for (int k = 0; k < 64; k++) s += lat[f * 64 + k] * W2[j * 64 + k];
        A[f][j] = s;
    }
    for (int idx = tid; idx < 16 * 64; idx += 256) {
        int r = idx >> 6, j = idx & 63;
        float s = b2[j];
        for (int k = 0; k < 64; k++) s += wgt[r * 64 + k] * W2[j * 64 + k];
        B[r][j] = s;
    }
    for (int idx = tid; idx < 8 * 64; idx += 256) {
        int f = idx >> 6, j = idx & 63;
        float s = b1[j];
        for (int k = 0; k < 64; k++) s += lat[f * 64 + k] * W1[j * 64 + k];
        g_latent_lin[idx] = s;
    }
    __syncthreads();
    {
        int f = (tid & 127) >> 4, r = tid & 15;
        float s = 0.0f;
        for (int j = 0; j < 64; j++) s += A[f][j] * B[r][j];
        S[f][r] = s;
    }
    __syncthreads();
    {
        int f = (tid & 127) >> 4, r = tid & 15;
        float s = bwa[r];
        for (int g = 0; g < 16; g++) s += S[f][g] * Wwa[r * 16 + g];
        D[f][r] = (s > 0.0f) ? s : 0.2f * s;
    }
    __syncthreads();
    if (tid < 8) {
        float m = -1e30f;
        for (int r = 0; r < 16; r++) m = fmaxf(m, D[tid][r]);
        float sum = 0.0f;
        for (int r = 0; r < 16; r++) { float e = expf(D[tid][r] - m); D[tid][r] = e; sum += e; }
        float inv = 1.0f / sum;
        for (int r = 0; r < 16; r++) D[tid][r] *= inv;
    }
    __syncthreads();
    for (int idx = tid; idx < 8 * 64; idx += 256) {
        int f = idx >> 6, c = idx & 63;
        float s = 0.0f;
        for (int r = 0; r < 16; r++) s += D[f][r] * wgt[r * 64 + c];
        g_latent_new[idx] = s;
        out_latent[idx]   = s;
    }
}

// scan phase 3 over aligned counts -> aligned offsets (accum resets counters)
__global__ void scan_final_kernel(int nEnt, int nUsr) {
    __shared__ int s[SCAN_CHUNK];
    int b = blockIdx.x, t = threadIdx.x;
    const int* cnt; int* off; int* cur; int base, n, pad;
    if (b < NBLK_E) { cnt = g_cntE; off = g_offE; cur = g_curE; base = b * SCAN_CHUNK; n = nEnt; pad = 3; }
    else            { cnt = g_cntU; off = g_offU; cur = g_curU; base = (b - NBLK_E) * SCAN_CHUNK; n = nUsr; pad = 1; }
    int bpre = g_bsum[b];
    int idx = base + t;
    int v = (idx < n) ? ((cnt[idx] + pad) & ~pad) : 0;
    s[t] = v; __syncthreads();
    for (int d = 1; d < SCAN_CHUNK; d <<= 1) {
        int x = s[t]; if (t >= d) x += s[t - d];
        __syncthreads(); s[t] = x; __syncthreads();
    }
    int excl = s[t] - v + bpre;
    if (idx < n) { off[idx] = excl; cur[idx] = excl; }
}

__global__ void scatter_kernel(const int* __restrict__ eidx,
                               const int* __restrict__ etype,
                               const int* __restrict__ irow,
                               const int* __restrict__ icol,
                               const float* __restrict__ ival,
                               int nE, int nnz) {
    int i = blockIdx.x * blockDim.x + threadIdx.x;
    if (i < nE) {
        int head = eidx[i];
        int tail = eidx[nE + i];
        int ty   = etype[i] - 1;
        int pos = atomicAdd(&g_curE[head], 1);
        g_skgp[pos] = tail | (ty << 17);
    } else {
        int j = i - nE;
        if (j < nnz) {
            int r = irow[j];
            int pos = atomicAdd(&g_curU[r], 1);
            g_sit[pos] = make_int2(icol[j], __float_as_int(ival[j]));
        }
    }
}

// ---------------------------------------------------------------------------
// Fused segment reduction: uniform int4 meta loads, double-buffered one
// iteration ahead (meta L2 latency hidden behind current group's gathers).
// One warp per segment, float2 per lane. Resets counters for next replay.
__global__ __launch_bounds__(256) void accum_kernel(
        const float* __restrict__ ent,
        const float* __restrict__ wgt,
        const float* __restrict__ usr,
        const float* __restrict__ W1,
        const float* __restrict__ b1,
        const float* __restrict__ Wua,
        const float* __restrict__ bua,
        float* __restrict__ ent_agg,
        float* __restrict__ usr_agg,
        int nEnt, int nUsr, int EB) {
    __shared__ float sbuf[SMEM_FLOATS];
    const unsigned FULL = 0xffffffffu;
    int t = threadIdx.x;
    int lane = t & 31;
    int wid = t >> 5;

    if (blockIdx.x < (unsigned)EB) {
        // ---------------- entity path ----------------
        for (int i = t; i < 1024; i += 256) sbuf[i] = wgt[i];
        __syncthreads();
        int w = blockIdx.x * 8 + wid;
        if (w >= nEnt) return;
        int start = g_offE[w];          // 16B-aligned element index
        int cnt   = g_cntE[w];
        if (lane == 0) g_cntE[w] = 0;   // reset for next replay
        const int* meta = g_skgp + start;

        float2 acc = make_float2(0.f, 0.f);
        int j = 0;
        if (cnt >= 4) {
            int4 mm = *reinterpret_cast<const int4*>(meta);   // prologue meta
            for (; j + 4 <= cnt; j += 4) {
                int4 cur = mm;
                if (j + 8 <= cnt)
                    mm = *reinterpret_cast<const int4*>(meta + j + 4);  // prefetch
                float2 e0 = *reinterpret_cast<const float2*>(ent + (size_t)(cur.x & 0x1FFFF) * 64 + lane * 2);
                float2 e1 = *reinterpret_cast<const float2*>(ent + (size_t)(cur.y & 0x1FFFF) * 64 + lane * 2);
                float2 e2 = *reinterpret_cast<const float2*>(ent + (size_t)(cur.z & 0x1FFFF) * 64 + lane * 2);
                float2 e3 = *reinterpret_cast<const float2*>(ent + (size_t)(cur.w & 0x1FFFF) * 64 + lane * 2);
                float2 w0 = *reinterpret_cast<const float2*>(sbuf + (cur.x >> 17) * 64 + lane * 2);
                float2 w1 = *reinterpret_cast<const float2*>(sbuf + (cur.y >> 17) * 64 + lane * 2);
                float2 w2 = *reinterpret_cast<const float2*>(sbuf + (cur.z >> 17) * 64 + lane * 2);
                float2 w3 = *reinterpret_cast<const float2*>(sbuf + (cur.w >> 17) * 64 + lane * 2);
                acc.x += e0.x * w0.x; acc.y += e0.y * w0.y;
                acc.x += e1.x * w1.x; acc.y += e1.y * w1.y;
                acc.x += e2.x * w2.x; acc.y += e2.y * w2.y;
                acc.x += e3.x * w3.x; acc.y += e3.y * w3.y;
            }
        }
        for (; j < cnt; j++) {
            int a = meta[j];
            float2 e  = *reinterpret_cast<const float2*>(ent + (size_t)(a & 0x1FFFF) * 64 + lane * 2);
            float2 wv = *reinterpret_cast<const float2*>(sbuf + (a >> 17) * 64 + lane * 2);
            acc.x += e.x * wv.x; acc.y += e.y * wv.y;
        }
        float inv = 1.0f / (float)(cnt > 1 ? cnt : 1);
        float2 r = make_float2(acc.x * inv, acc.y * inv);
        *reinterpret_cast<float2*>(ent_agg + (size_t)w * 64 + lane * 2) = r;
    } else {
        // ---------------- user path (accum + fused gating) ----------------
        for (int idx = t; idx < 4096; idx += 256) {
            int j = idx >> 6, k = idx & 63;
            sbuf[OFF_W1T + k * 66 + j] = W1[idx];
        }
        for (int idx = t; idx < 512; idx += 256) {
            sbuf[OFF_LAT + idx] = g_latent_lin[idx];
            sbuf[OFF_LN + idx]  = g_latent_new[idx];
        }
        if (t < 64) { sbuf[OFF_B1 + t] = b1[t]; sbuf[OFF_WUA + t] = Wua[t]; }
        if (t < 8)  sbuf[OFF_BUA + t] = bua[t];
        __syncthreads();

        int w = (blockIdx.x - EB) * 8 + wid;
        if (w >= nUsr) return;
        int start = g_offU[w];          // even element index -> 16B aligned
        int cnt   = g_cntU[w];
        if (lane == 0) g_cntU[w] = 0;   // reset for next replay
        const int2* meta = g_sit + start;

        float2 acc = make_float2(0.f, 0.f);
        int j = 0;
        if (cnt >= 4) {
            int4 ma = *reinterpret_cast<const int4*>(meta);       // edges 0,1
            int4 mb = *reinterpret_cast<const int4*>(meta + 2);   // edges 2,3
            for (; j + 4 <= cnt; j += 4) {
                int4 ca = ma, cb = mb;
                if (j + 8 <= cnt) {
                    ma = *reinterpret_cast<const int4*>(meta + j + 4);
                    mb = *reinterpret_cast<const int4*>(meta + j + 6);
                }
                float2 e0 = *reinterpret_cast<const float2*>(ent + (size_t)ca.x * 64 + lane * 2);
                float2 e1 = *reinterpret_cast<const float2*>(ent + (size_t)ca.z * 64 + lane * 2);
                float2 e2 = *reinterpret_cast<const float2*>(ent + (size_t)cb.x * 64 + lane * 2);
                float2 e3 = *reinterpret_cast<const float2*>(ent + (size_t)cb.z * 64 + lane * 2);
                float v0 = __int_as_float(ca.y);
                float v1 = __int_as_float(ca.w);
                float v2 = __int_as_float(cb.y);
                float v3 = __int_as_float(cb.w);
                acc.x += v0 * e0.x; acc.y += v0 * e0.y;
                acc.x += v1 * e1.x; acc.y += v1 * e1.y;
                acc.x += v2 * e2.x; acc.y += v2 * e2.y;
                acc.x += v3 * e3.x; acc.y += v3 * e3.y;
            }
        }
        for (; j < cnt; j++) {
            int2 m = meta[j];
            float v = __int_as_float(m.y);
            float2 e = *reinterpret_cast<const float2*>(ent + (size_t)m.x * 64 + lane * 2);
            acc.x += v * e.x; acc.y += v * e.y;
        }

        // gating: score = softmax(leaky(Wua @ (u_lin @ latent_lin^T) + bua))
        float2 uv = *reinterpret_cast<const float2*>(usr + (size_t)w * 64 + lane * 2);
        float* su = sbuf + OFF_SU + wid * 64;
        su[lane * 2] = uv.x; su[lane * 2 + 1] = uv.y;
        __syncwarp();

        float s0 = sbuf[OFF_B1 + 2 * lane], s1 = sbuf[OFF_B1 + 2 * lane + 1];
        #pragma unroll 8
        for (int k = 0; k < 64; k++) {
            float uk = su[k];
            float2 wv = *reinterpret_cast<const float2*>(sbuf + OFF_W1T + k * 66 + 2 * lane);
            s0 += uk * wv.x; s1 += uk * wv.y;
        }
        float sc[8];
        #pragma unroll
        for (int f = 0; f < 8; f++) {
            float2 lv = *reinterpret_cast<const float2*>(sbuf + OFF_LAT + f * 64 + lane * 2);
            sc[f] = s0 * lv.x + s1 * lv.y;
        }
        #pragma unroll
        for (int off = 16; off; off >>= 1) {
            #pragma unroll
            for (int f = 0; f < 8; f++) sc[f] += __shfl_xor_sync(FULL, sc[f], off);
        }
        float tv[8];
        #pragma unroll
        for (int f = 0; f < 8; f++) {
            float v = sbuf[OFF_BUA + f];
            #pragma unroll
            for (int g = 0; g < 8; g++) v += sc[g] * sbuf[OFF_WUA + f * 8 + g];
            tv[f] = (v > 0.f) ? v : 0.2f * v;
        }
        float mx = tv[0];
        #pragma unroll
        for (int f = 1; f < 8; f++) mx = fmaxf(mx, tv[f]);
        float ef[8], sum = 0.f;
        #pragma unroll
        for (int f = 0; f < 8; f++) { ef[f] = expf(tv[f] - mx); sum += ef[f]; }
        float sinv = 1.0f / sum;
        float2 g2 = make_float2(0.f, 0.f);
        #pragma unroll
        for (int f = 0; f < 8; f++) {
            float sf = ef[f] * sinv;
            float2 ln = *reinterpret_cast<const float2*>(sbuf + OFF_LN + f * 64 + lane * 2);
            g2.x += sf * ln.x; g2.y += sf * ln.y;
        }
        float2 r = make_float2(acc.x * (1.f + g2.x), acc.y * (1.f + g2.y));
        *reinterpret_cast<float2*>(usr_agg + (size_t)w * 64 + lane * 2) = r;
    }
}

// ---------------------------------------------------------------------------
extern "C" void kernel_launch(void* const* d_in, const int* in_sizes, int n_in,
                              void* d_out, int out_size) {
    const float* ent   = (const float*)d_in[0];
    const float* usr   = (const float*)d_in[1];
    const float* lat   = (const float*)d_in[2];
    const int*   eidx  = (const int*)  d_in[3];
    const int*   etype = (const int*)  d_in[4];
    const int*   irow  = (const int*)  d_in[5];
    const int*   icol  = (const int*)  d_in[6];
    const float* ival  = (const float*)d_in[7];
    const float* wgt   = (const float*)d_in[8];
    const float* Wua   = (const float*)d_in[10];
    const float* bua   = (const float*)d_in[11];
    const float* Wwa   = (const float*)d_in[12];
    const float* bwa   = (const float*)d_in[13];
    const float* W1    = (const float*)d_in[14];
    const float* b1    = (const float*)d_in[15];
    const float* W2    = (const float*)d_in[16];
    const float* b2    = (const float*)d_in[17];

    int nEnt = in_sizes[0] / 64;
    int nUsr = in_sizes[1] / 64;
    int nE   = in_sizes[4];
    int nnz  = in_sizes[5];

    float* out     = (float*)d_out;
    float* ent_agg = out;
    float* usr_agg = out + (size_t)nEnt * 64;
    float* lat_new = out + (size_t)nEnt * 64 + (size_t)nUsr * 64;

    // 1) histogram
    hist_kernel<<<(nE + nnz + 255) / 256, 256>>>(eidx, irow, nE, nnz);
    // 2) per-block aligned-count reduce
    scan_reduce_kernel<<<NBLK_E + NBLK_U, 256>>>(nEnt, nUsr);
    // 3) block-sum warp-scan + latent chain (single block)
    scan_mid_latent_kernel<<<1, 256>>>(lat, wgt, W1, b1, W2, b2, Wwa, bwa,
                                       lat_new, nEnt, nUsr);
    // 4) per-element aligned scan -> 16B-aligned segment offsets
    scan_final_kernel<<<NBLK_E + NBLK_U, SCAN_CHUNK>>>(nEnt, nUsr);
    // 5) counting-sort scatter
    scatter_kernel<<<(nE + nnz + 255) / 256, 256>>>(eidx, etype, irow, icol, ival, nE, nnz);
    // 6) fused segment reductions + user gating (+counter reset)
    int EB = (nEnt + 7) / 8;
    int UB = (nUsr + 7) / 8;
    accum_kernel<<<EB + UB, 256>>>(ent, wgt, usr, W1, b1, Wua, bua,
                                   ent_agg, usr_agg, nEnt, nUsr, EB);
}

// round 14
// speedup vs baseline: 1.6222x; 1.6222x over previous
#include <cuda_runtime.h>
#include <math.h>

// ---------------------------------------------------------------------------
// Aggregator: CSR-ified KG gather-scatter-mean + COO spmm + latent attention.
// Strategy: counting sort edges by destination each launch (hist -> scan ->
// scatter), then one warp per destination accumulates in registers and writes
// the row ONCE (no float atomics at all).
// Output (float32): [entity_agg 100000*64 | user_agg 50000*64 | latent_new 8*64]
// ---------------------------------------------------------------------------

#define N_ENT 100000
#define N_USR 50000
#define N_EDG 2000000
#define N_NNZ 2000000
#define SCAN_CHUNK 1024
#define NBLK_E ((N_ENT + SCAN_CHUNK - 1) / SCAN_CHUNK)   // 98
#define NBLK_U ((N_USR + SCAN_CHUNK - 1) / SCAN_CHUNK)   // 49

__device__ int  g_cntE[N_ENT];
__device__ int  g_cntU[N_USR];
__device__ int  g_offE[N_ENT + 1];
__device__ int  g_offU[N_USR + 1];
__device__ int  g_curE[N_ENT];
__device__ int  g_curU[N_USR];
__device__ int  g_bsum[NBLK_E + NBLK_U];
__device__ int  g_skgp[N_EDG];  // packed: tail | (type-1)<<17, sorted by head
__device__ int2 g_sit[N_NNZ];   // {col, bits(val)} sorted by row

__device__ float g_latent_lin[8 * 64];
__device__ float g_latent_new[8 * 64];

// smem layout for fused accum kernel (floats)
#define OFF_W1T 0              // 64 * 66 transposed+padded W1
#define OFF_LAT 4224           // 8 * 64
#define OFF_LN  4736           // 8 * 64
#define OFF_SU  5248           // 8 warps * 64
#define OFF_B1  5760           // 64
#define OFF_WUA 5824           // 64
#define OFF_BUA 5888           // 8
#define SMEM_FLOATS 5896

// ---------------------------------------------------------------------------
__global__ void zero_cnt_kernel(int nEnt, int nUsr) {
    int i = blockIdx.x * blockDim.x + threadIdx.x;
    if (i < nEnt) g_cntE[i] = 0;
    else { int j = i - nEnt; if (j < nUsr) g_cntU[j] = 0; }
}

__global__ void hist_kernel(const int* __restrict__ eidx,
                            const int* __restrict__ irow,
                            int nE, int nnz) {
    int i = blockIdx.x * blockDim.x + threadIdx.x;
    if (i < nE) atomicAdd(&g_cntE[eidx[i]], 1);
    else { int j = i - nE; if (j < nnz) atomicAdd(&g_cntU[irow[j]], 1); }
}

__global__ void scan_reduce_kernel(int nEnt, int nUsr) {
    __shared__ int s[256];
    int b = blockIdx.x, t = threadIdx.x;
    const int* src; int base, n;
    if (b < NBLK_E) { src = g_cntE; base = b * SCAN_CHUNK; n = nEnt; }
    else            { src = g_cntU; base = (b - NBLK_E) * SCAN_CHUNK; n = nUsr; }
    int sum = 0;
    for (int i = t; i < SCAN_CHUNK; i += 256) {
        int idx = base + i;
        if (idx < n) sum += src[idx];
    }
    s[t] = sum; __syncthreads();
    for (int d = 128; d > 0; d >>= 1) { if (t < d) s[t] += s[t + d]; __syncthreads(); }
    if (t == 0) g_bsum[b] = s[0];
}

__global__ void scan_mid_kernel(int nEnt, int nUsr) {
    __shared__ int s[128];
    int t = threadIdx.x;
    int v = (t < NBLK_E) ? g_bsum[t] : 0;
    s[t] = v; __syncthreads();
    for (int d = 1; d < 128; d <<= 1) {
        int x = s[t]; if (t >= d) x += s[t - d];
        __syncthreads(); s[t] = x; __syncthreads();
    }
    if (t < NBLK_E) g_bsum[t] = s[t] - v;
    if (t == NBLK_E - 1) g_offE[nEnt] = s[t];
    __syncthreads();
    v = (t < NBLK_U) ? g_bsum[NBLK_E + t] : 0;
    s[t] = v; __syncthreads();
    for (int d = 1; d < 128; d <<= 1) {
        int x = s[t]; if (t >= d) x += s[t - d];
        __syncthreads(); s[t] = x; __syncthreads();
    }
    if (t < NBLK_U) g_bsum[NBLK_E + t] = s[t] - v;
    if (t == NBLK_U - 1) g_offU[nUsr] = s[t];
}

__global__ void scan_final_kernel(int nEnt, int nUsr) {
    __shared__ int s[SCAN_CHUNK];
    int b = blockIdx.x, t = threadIdx.x;
    const int* cnt; int* off; int* cur; int base, n;
    if (b < NBLK_E) { cnt = g_cntE; off = g_offE; cur = g_curE; base = b * SCAN_CHUNK; n = nEnt; }
    else            { cnt = g_cntU; off = g_offU; cur = g_curU; base = (b - NBLK_E) * SCAN_CHUNK; n = nUsr; }
    int bpre = g_bsum[b];
    int idx = base + t;
    int v = (idx < n) ? cnt[idx] : 0;
    s[t] = v; __syncthreads();
    for (int d = 1; d < SCAN_CHUNK; d <<= 1) {
        int x = s[t]; if (t >= d) x += s[t - d];
        __syncthreads(); s[t] = x; __syncthreads();
    }
    int excl = s[t] - v + bpre;
    if (idx < n) { off[idx] = excl; cur[idx] = excl; }
}

__global__ void scatter_kernel(const int* __restrict__ eidx,
                               const int* __restrict__ etype,
                               const int* __restrict__ irow,
                               const int* __restrict__ icol,
                               const float* __restrict__ ival,
                               int nE, int nnz) {
    int i = blockIdx.x * blockDim.x + threadIdx.x;
    if (i < nE) {
        int head = eidx[i];
        int tail = eidx[nE + i];
        int ty   = etype[i] - 1;
        int pos = atomicAdd(&g_curE[head], 1);
        g_skgp[pos] = tail | (ty << 17);
    } else {
        int j = i - nE;
        if (j < nnz) {
            int r = irow[j];
            int pos = atomicAdd(&g_curU[r], 1);
            g_sit[pos] = make_int2(icol[j], __float_as_int(ival[j]));
        }
    }
}

// ---------------------------------------------------------------------------
// Tiny latent chain (single block, 128 threads).
__global__ void latent_kernel(const float* __restrict__ lat,
                              const float* __restrict__ wgt,
                              const float* __restrict__ W1, const float* __restrict__ b1,
                              const float* __restrict__ W2, const float* __restrict__ b2,
                              const float* __restrict__ Wwa, const float* __restrict__ bwa,
                              float* __restrict__ out_latent) {
    __shared__ float A[8][64];
    __shared__ float B[16][64];
    __shared__ float S[8][16];
    __shared__ float D[8][16];
    int tid = threadIdx.x;

    for (int idx = tid; idx < 8 * 64; idx += 128) {
        int f = idx >> 6, j = idx & 63;
        float s = b2[j];
        for (int k = 0; k < 64; k++) s += lat[f * 64 + k] * W2[j * 64 + k];
        A[f][j] = s;
    }
    for (int idx = tid; idx < 16 * 64; idx += 128) {
        int r = idx >> 6, j = idx & 63;
        float s = b2[j];
        for (int k = 0; k < 64; k++) s += wgt[r * 64 + k] * W2[j * 64 + k];
        B[r][j] = s;
    }
    for (int idx = tid; idx < 8 * 64; idx += 128) {
        int f = idx >> 6, j = idx & 63;
        float s = b1[j];
        for (int k = 0; k < 64; k++) s += lat[f * 64 + k] * W1[j * 64 + k];
        g_latent_lin[idx] = s;
    }
    __syncthreads();

    {
        int f = tid >> 4, r = tid & 15;
        float s = 0.0f;
        for (int j = 0; j < 64; j++) s += A[f][j] * B[r][j];
        S[f][r] = s;
    }
    __syncthreads();
    {
        int f = tid >> 4, r = tid & 15;
        float s = bwa[r];
        for (int g = 0; g < 16; g++) s += S[f][g] * Wwa[r * 16 + g];
        D[f][r] = (s > 0.0f) ? s : 0.2f * s;
    }
    __syncthreads();
    if (tid < 8) {
        float m = -1e30f;
        for (int r = 0; r < 16; r++) m = fmaxf(m, D[tid][r]);
        float sum = 0.0f;
        for (int r = 0; r < 16; r++) { float e = expf(D[tid][r] - m); D[tid][r] = e; sum += e; }
        float inv = 1.0f / sum;
        for (int r = 0; r < 16; r++) D[tid][r] *= inv;
    }
    __syncthreads();
    for (int idx = tid; idx < 8 * 64; idx += 128) {
        int f = idx >> 6, c = idx & 63;
        float s = 0.0f;
        for (int r = 0; r < 16; r++) s += D[f][r] * wgt[r * 64 + c];
        g_latent_new[idx] = s;
        out_latent[idx]   = s;
    }
}

// ---------------------------------------------------------------------------
// Fused segment reduction: entity blocks [0, EB), user blocks [EB, EB+UB).
// One warp per segment, lane owns channels 2*lane, 2*lane+1. MLP-4 inner loop.
// User path applies the attention gating inline (no extra pass over user_agg).
__global__ __launch_bounds__(256) void accum_kernel(
        const float* __restrict__ ent,
        const float* __restrict__ wgt,
        const float* __restrict__ usr,
        const float* __restrict__ W1,
        const float* __restrict__ b1,
        const float* __restrict__ Wua,
        const float* __restrict__ bua,
        float* __restrict__ ent_agg,
        float* __restrict__ usr_agg,
        int nEnt, int nUsr, int EB) {
    __shared__ float sbuf[SMEM_FLOATS];
    const unsigned FULL = 0xffffffffu;
    int t = threadIdx.x;
    int lane = t & 31;
    int wid = t >> 5;

    if (blockIdx.x < EB) {
        // ---------------- entity path ----------------
        for (int i = t; i < 1024; i += 256) sbuf[i] = wgt[i];
        __syncthreads();
        int w = blockIdx.x * 8 + wid;
        if (w >= nEnt) return;
        int start = g_offE[w], end = g_offE[w + 1];
        float2 acc = make_float2(0.f, 0.f);
        int base = start, n = end - start;
        while (n > 0) {
            int take = n < 32 ? n : 32;
            int m = (lane < take) ? g_skgp[base + lane] : 0;
            int j = 0;
            for (; j + 4 <= take; j += 4) {
                int a0 = __shfl_sync(FULL, m, j);
                int a1 = __shfl_sync(FULL, m, j + 1);
                int a2 = __shfl_sync(FULL, m, j + 2);
                int a3 = __shfl_sync(FULL, m, j + 3);
                float2 e0 = *reinterpret_cast<const float2*>(ent + (size_t)(a0 & 0x1FFFF) * 64 + lane * 2);
                float2 e1 = *reinterpret_cast<const float2*>(ent + (size_t)(a1 & 0x1FFFF) * 64 + lane * 2);
                float2 e2 = *reinterpret_cast<const float2*>(ent + (size_t)(a2 & 0x1FFFF) * 64 + lane * 2);
                float2 e3 = *reinterpret_cast<const float2*>(ent + (size_t)(a3 & 0x1FFFF) * 64 + lane * 2);
                float2 w0 = *reinterpret_cast<const float2*>(sbuf + (a0 >> 17) * 64 + lane * 2);
                float2 w1 = *reinterpret_cast<const float2*>(sbuf + (a1 >> 17) * 64 + lane * 2);
                float2 w2 = *reinterpret_cast<const float2*>(sbuf + (a2 >> 17) * 64 + lane * 2);
                float2 w3 = *reinterpret_cast<const float2*>(sbuf + (a3 >> 17) * 64 + lane * 2);
                acc.x += e0.x * w0.x; acc.y += e0.y * w0.y;
                acc.x += e1.x * w1.x; acc.y += e1.y * w1.y;
                acc.x += e2.x * w2.x; acc.y += e2.y * w2.y;
                acc.x += e3.x * w3.x; acc.y += e3.y * w3.y;
            }
            for (; j < take; j++) {
                int a = __shfl_sync(FULL, m, j);
                float2 e  = *reinterpret_cast<const float2*>(ent + (size_t)(a & 0x1FFFF) * 64 + lane * 2);
                float2 wv = *reinterpret_cast<const float2*>(sbuf + (a >> 17) * 64 + lane * 2);
                acc.x += e.x * wv.x; acc.y += e.y * wv.y;
            }
            base += take; n -= take;
        }
        int cnt = end - start;
        float inv = 1.0f / (float)(cnt > 1 ? cnt : 1);
        float2 r = make_float2(acc.x * inv, acc.y * inv);
        *reinterpret_cast<float2*>(ent_agg + (size_t)w * 64 + lane * 2) = r;
    } else {
        // ---------------- user path (accum + fused gating) ----------------
        for (int idx = t; idx < 4096; idx += 256) {
            int j = idx >> 6, k = idx & 63;
            sbuf[OFF_W1T + k * 66 + j] = W1[idx];
        }
        for (int idx = t; idx < 512; idx += 256) {
            sbuf[OFF_LAT + idx] = g_latent_lin[idx];
            sbuf[OFF_LN + idx]  = g_latent_new[idx];
        }
        if (t < 64) { sbuf[OFF_B1 + t] = b1[t]; sbuf[OFF_WUA + t] = Wua[t]; }
        if (t < 8)  sbuf[OFF_BUA + t] = bua[t];
        __syncthreads();

        int w = (blockIdx.x - EB) * 8 + wid;
        if (w >= nUsr) return;
        int start = g_offU[w], end = g_offU[w + 1];
        float2 acc = make_float2(0.f, 0.f);
        int base = start, n = end - start;
        while (n > 0) {
            int take = n < 32 ? n : 32;
            int2 m = (lane < take) ? g_sit[base + lane] : make_int2(0, 0);
            int j = 0;
            for (; j + 4 <= take; j += 4) {
                int c0 = __shfl_sync(FULL, m.x, j);
                int c1 = __shfl_sync(FULL, m.x, j + 1);
                int c2 = __shfl_sync(FULL, m.x, j + 2);
                int c3 = __shfl_sync(FULL, m.x, j + 3);
                float v0 = __int_as_float(__shfl_sync(FULL, m.y, j));
                float v1 = __int_as_float(__shfl_sync(FULL, m.y, j + 1));
                float v2 = __int_as_float(__shfl_sync(FULL, m.y, j + 2));
                float v3 = __int_as_float(__shfl_sync(FULL, m.y, j + 3));
                float2 e0 = *reinterpret_cast<const float2*>(ent + (size_t)c0 * 64 + lane * 2);
                float2 e1 = *reinterpret_cast<const float2*>(ent + (size_t)c1 * 64 + lane * 2);
                float2 e2 = *reinterpret_cast<const float2*>(ent + (size_t)c2 * 64 + lane * 2);
                float2 e3 = *reinterpret_cast<const float2*>(ent + (size_t)c3 * 64 + lane * 2);
                acc.x += v0 * e0.x; acc.y += v0 * e0.y;
                acc.x += v1 * e1.x; acc.y += v1 * e1.y;
                acc.x += v2 * e2.x; acc.y += v2 * e2.y;
                acc.x += v3 * e3.x; acc.y += v3 * e3.y;
            }
            for (; j < take; j++) {
                int   c = __shfl_sync(FULL, m.x, j);
                float v = __int_as_float(__shfl_sync(FULL, m.y, j));
                float2 e = *reinterpret_cast<const float2*>(ent + (size_t)c * 64 + lane * 2);
                acc.x += v * e.x; acc.y += v * e.y;
            }
            base += take; n -= take;
        }

        // gating: score = softmax(leaky(Wua @ (u_lin @ latent_lin^T) + bua))
        float2 uv = *reinterpret_cast<const float2*>(usr + (size_t)w * 64 + lane * 2);
        float* su = sbuf + OFF_SU + wid * 64;
        su[lane * 2] = uv.x; su[lane * 2 + 1] = uv.y;
        __syncwarp();

        float s0 = sbuf[OFF_B1 + 2 * lane], s1 = sbuf[OFF_B1 + 2 * lane + 1];
        #pragma unroll 8
        for (int k = 0; k < 64; k++) {
            float uk = su[k];
            float2 wv = *reinterpret_cast<const float2*>(sbuf + OFF_W1T + k * 66 + 2 * lane);
            s0 += uk * wv.x; s1 += uk * wv.y;
        }
        float sc[8];
        #pragma unroll
        for (int f = 0; f < 8; f++) {
            float2 lv = *reinterpret_cast<const float2*>(sbuf + OFF_LAT + f * 64 + lane * 2);
            sc[f] = s0 * lv.x + s1 * lv.y;
        }
        #pragma unroll
        for (int off = 16; off; off >>= 1) {
            #pragma unroll
            for (int f = 0; f < 8; f++) sc[f] += __shfl_xor_sync(FULL, sc[f], off);
        }
        float tv[8];
        #pragma unroll
        for (int f = 0; f < 8; f++) {
            float v = sbuf[OFF_BUA + f];
            #pragma unroll
            for (int g = 0; g < 8; g++) v += sc[g] * sbuf[OFF_WUA + f * 8 + g];
            tv[f] = (v > 0.f) ? v : 0.2f * v;
        }
        float mx = tv[0];
        #pragma unroll
        for (int f = 1; f < 8; f++) mx = fmaxf(mx, tv[f]);
        float ef[8], sum = 0.f;
        #pragma unroll
        for (int f = 0; f < 8; f++) { ef[f] = expf(tv[f] - mx); sum += ef[f]; }
        float sinv = 1.0f / sum;
        float2 g2 = make_float2(0.f, 0.f);
        #pragma unroll
        for (int f = 0; f < 8; f++) {
            float sf = ef[f] * sinv;
            float2 ln = *reinterpret_cast<const float2*>(sbuf + OFF_LN + f * 64 + lane * 2);
            g2.x += sf * ln.x; g2.y += sf * ln.y;
        }
        float2 r = make_float2(acc.x * (1.f + g2.x), acc.y * (1.f + g2.y));
        *reinterpret_cast<float2*>(usr_agg + (size_t)w * 64 + lane * 2) = r;
    }
}

// ---------------------------------------------------------------------------
extern "C" void kernel_launch(void* const* d_in, const int* in_sizes, int n_in,
                              void* d_out, int out_size) {
    const float* ent   = (const float*)d_in[0];
    const float* usr   = (const float*)d_in[1];
    const float* lat   = (const float*)d_in[2];
    const int*   eidx  = (const int*)  d_in[3];
    const int*   etype = (const int*)  d_in[4];
    const int*   irow  = (const int*)  d_in[5];
    const int*   icol  = (const int*)  d_in[6];
    const float* ival  = (const float*)d_in[7];
    const float* wgt   = (const float*)d_in[8];
    const float* Wua   = (const float*)d_in[10];
    const float* bua   = (const float*)d_in[11];
    const float* Wwa   = (const float*)d_in[12];
    const float* bwa   = (const float*)d_in[13];
    const float* W1    = (const float*)d_in[14];
    const float* b1    = (const float*)d_in[15];
    const float* W2    = (const float*)d_in[16];
    const float* b2    = (const float*)d_in[17];

    int nEnt = in_sizes[0] / 64;   // 100000
    int nUsr = in_sizes[1] / 64;   // 50000
    int nE   = in_sizes[4];        // 2000000
    int nnz  = in_sizes[5];        // 2000000

    float* out     = (float*)d_out;
    float* ent_agg = out;
    float* usr_agg = out + (size_t)nEnt * 64;
    float* lat_new = out + (size_t)nEnt * 64 + (size_t)nUsr * 64;

    // CSR build
    zero_cnt_kernel<<<(nEnt + nUsr + 255) / 256, 256>>>(nEnt, nUsr);
    hist_kernel<<<(nE + nnz + 255) / 256, 256>>>(eidx, irow, nE, nnz);
    scan_reduce_kernel<<<NBLK_E + NBLK_U, 256>>>(nEnt, nUsr);
    scan_mid_kernel<<<1, 128>>>(nEnt, nUsr);
    scan_final_kernel<<<NBLK_E + NBLK_U, SCAN_CHUNK>>>(nEnt, nUsr);
    scatter_kernel<<<(nE + nnz + 255) / 256, 256>>>(eidx, etype, irow, icol, ival, nE, nnz);

    // small dense chain (independent of CSR)
    latent_kernel<<<1, 128>>>(lat, wgt, W1, b1, W2, b2, Wwa, bwa, lat_new);

    // fused segment reductions + user gating
    int EB = (nEnt + 7) / 8;
    int UB = (nUsr + 7) / 8;
    accum_kernel<<<EB + UB, 256>>>(ent, wgt, usr, W1, b1, Wua, bua,
                                   ent_agg, usr_agg, nEnt, nUsr, EB);
}